// round 6
// baseline (speedup 1.0000x reference)
#include <cuda_runtime.h>
#include <cuda_fp16.h>
#include <math.h>

#define BATCH 4096
#define FEAT  40960
#define HID   1024
#define HID2  2048
#define NL1   64
#define NL2   32
#define GRP   32
#define NGRP  (BATCH / GRP)     // 128

// ---------------- static device scratch (no allocs allowed) ----------------
__device__ __half g_ftT[(size_t)FEAT * HID];    // 83.9 MB: ft_w^T [FEAT][HID] fp16
__device__ __half g_h1[(size_t)BATCH * HID2];   // 16.8 MB: clipped FT output fp16
__device__ __half g_l1w[(size_t)NL1 * HID2];    // 256 KB: l1_w fp16
__device__ int    g_done;                       // transpose-completion counter
__device__ int    g_grp[NGRP];                  // per-group h1-completion counters

// =========================================================================
// Prep: reset counters + convert l1_w to fp16. grid 128 x 256.
// =========================================================================
__global__ __launch_bounds__(256) void prep_kernel(const float* __restrict__ l1_w)
{
    const int i = blockIdx.x * 256 + threadIdx.x;     // 32768 threads
#pragma unroll
    for (int u = 0; u < 4; u++)
        g_l1w[i + u * 32768] = __float2half(l1_w[i + u * 32768]);
    if (blockIdx.x == 0 && threadIdx.x < NGRP) g_grp[threadIdx.x] = 0;
    if (i == 0) g_done = 0;
}

// =========================================================================
// Mega-kernel:
//   CTAs [0, NT)        : transpose ft_w -> g_ftT (fp16), signal g_done.
//   CTAs [NT, NT+BATCH) : scan -> wait -> gather -> h1 -> group counter;
//                         the 32nd finisher of each 32-row group runs the MLP.
// =========================================================================
#define T1      256
#define NT      512
#define MAXIDX  256
#define NTILE_F (FEAT / 32)                 // 1280
#define NTILES  (NTILE_F * (HID / 64))      // 20480
#define CHUNK   64
#define NCH     (HID2 / CHUNK)              // 32

__global__ __launch_bounds__(T1) void mega_kernel(
    const float* __restrict__ wf,    // [B, FEAT]
    const float* __restrict__ bfeat, // [B, FEAT]
    const float* __restrict__ stm,   // [B, 1]
    const float* __restrict__ ftw,   // [HID, FEAT]
    const float* __restrict__ ft_b,  // [HID]
    const float* __restrict__ l1_b,  // [64]
    const float* __restrict__ l2_w,  // [32, 64]
    const float* __restrict__ l2_b,  // [32]
    const float* __restrict__ l3_w,  // [1, 32]
    const float* __restrict__ l3_b,  // [1]
    float* __restrict__ out, int out_size)
{
    __shared__ union {
        float tile[64][33];                                  // transpose (8.4 KB)
        struct { int idxW[MAXIDX]; int idxB[MAXIDX]; int cw, cb; } s;
        struct {                                             // group MLP (~30 KB)
            __align__(16) float  hst[CHUNK][36];
            __align__(4)  __half wst[CHUNK][66];
            float h2[GRP][NL1 + 1];
            float h3[GRP][NL2 + 1];
        } m;
    } sm;
    __shared__ int sm_flag;

    const int tid = threadIdx.x;

    if (blockIdx.x < NT) {
        // ---------------- transpose ----------------
        for (int t = blockIdx.x; t < NTILES; t += NT) {
            const int f0 = (t % NTILE_F) * 32;
            const int h0 = (t / NTILE_F) * 64;
#pragma unroll
            for (int u = 0; u < 8; u++) {
                int idx = tid + u * T1;
                int hl = idx >> 5, fl = idx & 31;
                sm.tile[hl][fl] = __ldcs(ftw + (size_t)(h0 + hl) * FEAT + f0 + fl);
            }
            __syncthreads();
#pragma unroll
            for (int u = 0; u < 4; u++) {
                int idx = tid + u * T1;
                int fl = idx >> 5, hp = idx & 31;
                __half2 v = __floats2half2_rn(sm.tile[2 * hp][fl], sm.tile[2 * hp + 1][fl]);
                *reinterpret_cast<__half2*>(g_ftT + (size_t)(f0 + fl) * HID + h0 + 2 * hp) = v;
            }
            __syncthreads();
        }
        __threadfence();
        __syncthreads();
        if (tid == 0) atomicAdd(&g_done, 1);
        return;
    }

    // ---------------- scan ----------------
    const int b = blockIdx.x - NT;

    if (tid == 0) { sm.s.cw = 0; sm.s.cb = 0; }
    __syncthreads();
    {
        const float4* pw = (const float4*)(wf    + (size_t)b * FEAT);
        const float4* pb = (const float4*)(bfeat + (size_t)b * FEAT);
        for (int base = 0; base < FEAT / 4; base += 4 * T1) {
            float4 v[4], w[4];
#pragma unroll
            for (int u = 0; u < 4; u++) {
                v[u] = __ldcs(pw + base + tid + u * T1);
                w[u] = __ldcs(pb + base + tid + u * T1);
            }
#pragma unroll
            for (int u = 0; u < 4; u++) {
                int i = base + tid + u * T1;
                if (v[u].x != 0.f) { int q = atomicAdd(&sm.s.cw, 1); if (q < MAXIDX) sm.s.idxW[q] = 4*i;   }
                if (v[u].y != 0.f) { int q = atomicAdd(&sm.s.cw, 1); if (q < MAXIDX) sm.s.idxW[q] = 4*i+1; }
                if (v[u].z != 0.f) { int q = atomicAdd(&sm.s.cw, 1); if (q < MAXIDX) sm.s.idxW[q] = 4*i+2; }
                if (v[u].w != 0.f) { int q = atomicAdd(&sm.s.cw, 1); if (q < MAXIDX) sm.s.idxW[q] = 4*i+3; }
                if (w[u].x != 0.f) { int q = atomicAdd(&sm.s.cb, 1); if (q < MAXIDX) sm.s.idxB[q] = 4*i;   }
                if (w[u].y != 0.f) { int q = atomicAdd(&sm.s.cb, 1); if (q < MAXIDX) sm.s.idxB[q] = 4*i+1; }
                if (w[u].z != 0.f) { int q = atomicAdd(&sm.s.cb, 1); if (q < MAXIDX) sm.s.idxB[q] = 4*i+2; }
                if (w[u].w != 0.f) { int q = atomicAdd(&sm.s.cb, 1); if (q < MAXIDX) sm.s.idxB[q] = 4*i+3; }
            }
        }
    }
    __syncthreads();

    // wait for transpose completion (~50us of scan work precedes this)
    if (tid == 0) {
        while (atomicAdd(&g_done, 0) < NT) __nanosleep(128);
    }
    __syncthreads();
    __threadfence();

    // ---------------- gather ----------------
    const float4 bias = *reinterpret_cast<const float4*>(ft_b + 4 * tid);
    float4 accW = bias, accB = bias;
    const int nW = min(sm.s.cw, MAXIDX);
#pragma unroll 4
    for (int j = 0; j < nW; j++) {
        const uint2 raw = *reinterpret_cast<const uint2*>(
            g_ftT + (size_t)sm.s.idxW[j] * HID + 4 * tid);
        const float2 lo = __half22float2(*reinterpret_cast<const __half2*>(&raw.x));
        const float2 hi = __half22float2(*reinterpret_cast<const __half2*>(&raw.y));
        accW.x += lo.x; accW.y += lo.y; accW.z += hi.x; accW.w += hi.y;
    }
    const int nB = min(sm.s.cb, MAXIDX);
#pragma unroll 4
    for (int j = 0; j < nB; j++) {
        const uint2 raw = *reinterpret_cast<const uint2*>(
            g_ftT + (size_t)sm.s.idxB[j] * HID + 4 * tid);
        const float2 lo = __half22float2(*reinterpret_cast<const __half2*>(&raw.x));
        const float2 hi = __half22float2(*reinterpret_cast<const __half2*>(&raw.y));
        accB.x += lo.x; accB.y += lo.y; accB.z += hi.x; accB.w += hi.y;
    }

    // stm select + clip + store h1 (fp16)
    {
        const float s = __ldg(stm + b);
        float cw[4] = {fminf(fmaxf(accW.x,0.f),1.f), fminf(fmaxf(accW.y,0.f),1.f),
                       fminf(fmaxf(accW.z,0.f),1.f), fminf(fmaxf(accW.w,0.f),1.f)};
        float cb[4] = {fminf(fmaxf(accB.x,0.f),1.f), fminf(fmaxf(accB.y,0.f),1.f),
                       fminf(fmaxf(accB.z,0.f),1.f), fminf(fmaxf(accB.w,0.f),1.f)};
        __half* o = g_h1 + (size_t)b * HID2;
        uint2 pf, ps;
        *reinterpret_cast<__half2*>(&pf.x) = __floats2half2_rn(
            s*cw[0]+(1.f-s)*cb[0], s*cw[1]+(1.f-s)*cb[1]);
        *reinterpret_cast<__half2*>(&pf.y) = __floats2half2_rn(
            s*cw[2]+(1.f-s)*cb[2], s*cw[3]+(1.f-s)*cb[3]);
        *reinterpret_cast<__half2*>(&ps.x) = __floats2half2_rn(
            s*cb[0]+(1.f-s)*cw[0], s*cb[1]+(1.f-s)*cw[1]);
        *reinterpret_cast<__half2*>(&ps.y) = __floats2half2_rn(
            s*cb[2]+(1.f-s)*cw[2], s*cb[3]+(1.f-s)*cw[3]);
        *reinterpret_cast<uint2*>(o + 4 * tid)       = pf;
        *reinterpret_cast<uint2*>(o + HID + 4 * tid) = ps;
    }

    // ---------------- group completion: last arriver runs the 32-row MLP ----------------
    const int g = b >> 5;
    __threadfence();   // publish h1 before counting
    __syncthreads();   // all warps' stores issued before tid 0 counts
    if (tid == 0) {
        int old = atomicAdd(&g_grp[g], 1);
        sm_flag = (old == GRP - 1);
    }
    __syncthreads();
    if (!sm_flag) return;
    __threadfence();   // acquire: see other CTAs' h1

    // ===== 32-row MLP for rows [32g, 32g+32) =====
    const int row0 = g * GRP;
    const int tx = tid & 31;       // out pair {2tx, 2tx+1}
    const int ty = tid >> 5;       // row quad {4ty..4ty+3}

    float acc[4][2];
#pragma unroll
    for (int i = 0; i < 4; i++) { acc[i][0] = 0.f; acc[i][1] = 0.f; }

    const __half2* l1w2 = reinterpret_cast<const __half2*>(g_l1w);

    for (int c = 0; c < NCH; c++) {
        const int kc = c * CHUNK;
        __syncthreads();
        // stage h1 chunk: 32 rows x 64 k  (1024 half2, 4/thread), transposed [k][r]
#pragma unroll
        for (int u = 0; u < 4; u++) {
            int idx = tid + u * T1; int r = idx >> 5, kp = idx & 31;
            float2 f = __half22float2(*reinterpret_cast<const __half2*>(
                g_h1 + (size_t)(row0 + r) * HID2 + kc + 2 * kp));
            sm.m.hst[2 * kp][r]     = f.x;
            sm.m.hst[2 * kp + 1][r] = f.y;
        }
        // stage weights chunk: 64 o x 64 k (2048 half2, 8/thread) -> [k][o]
#pragma unroll
        for (int u = 0; u < 8; u++) {
            int idx = tid + u * T1; int o = idx >> 5, kp = idx & 31;
            __half2 wv = __ldg(l1w2 + (size_t)o * (HID2 / 2) + kc / 2 + kp);
            sm.m.wst[2 * kp][o]     = __low2half(wv);
            sm.m.wst[2 * kp + 1][o] = __high2half(wv);
        }
        __syncthreads();
#pragma unroll 16
        for (int k = 0; k < CHUNK; k++) {
            const float4 h = *reinterpret_cast<const float4*>(&sm.m.hst[k][4 * ty]);
            const float2 w = __half22float2(
                *reinterpret_cast<const __half2*>(&sm.m.wst[k][2 * tx]));
            acc[0][0] = fmaf(h.x, w.x, acc[0][0]); acc[0][1] = fmaf(h.x, w.y, acc[0][1]);
            acc[1][0] = fmaf(h.y, w.x, acc[1][0]); acc[1][1] = fmaf(h.y, w.y, acc[1][1]);
            acc[2][0] = fmaf(h.z, w.x, acc[2][0]); acc[2][1] = fmaf(h.z, w.y, acc[2][1]);
            acc[3][0] = fmaf(h.w, w.x, acc[3][0]); acc[3][1] = fmaf(h.w, w.y, acc[3][1]);
        }
    }
    __syncthreads();

    // h2 = clip(l1 + bias)
#pragma unroll
    for (int i = 0; i < 4; i++) {
#pragma unroll
        for (int j = 0; j < 2; j++) {
            float v = acc[i][j] + __ldg(l1_b + 2 * tx + j);
            sm.m.h2[4 * ty + i][2 * tx + j] = fminf(fmaxf(v, 0.f), 1.f);
        }
    }
    __syncthreads();

    // l2: 32 rows x 32 outs, one per thread... 1024 = T1*4
    for (int p = tid; p < GRP * NL2; p += T1) {
        int r = p >> 5, o = p & 31;
        float s = __ldg(l2_b + o);
        const float* wrow = l2_w + o * NL1;
#pragma unroll
        for (int k = 0; k < NL1; k++) s = fmaf(sm.m.h2[r][k], __ldg(wrow + k), s);
        sm.m.h3[r][o] = fminf(fmaxf(s, 0.f), 1.f);
    }
    __syncthreads();

    // l3 + sigmoid
    if (tid < GRP) {
        float s = __ldg(l3_b);
#pragma unroll
        for (int k = 0; k < NL2; k++) s = fmaf(sm.m.h3[tid][k], __ldg(l3_w + k), s);
        float sig = 1.f / (1.f + expf(-s));
        int r = row0 + tid;
        if (out_size >= 2 * BATCH) {
            out[r]         = sig;
            out[BATCH + r] = s;
        } else {
            out[r] = sig;
        }
    }
}

// =========================================================================
extern "C" void kernel_launch(void* const* d_in, const int* in_sizes, int n_in,
                              void* d_out, int out_size)
{
    const float* wf    = (const float*)d_in[0];
    const float* bfeat = (const float*)d_in[1];
    const float* stm   = (const float*)d_in[2];
    const float* ft_w  = (const float*)d_in[3];
    const float* ft_b  = (const float*)d_in[4];
    const float* l1_w  = (const float*)d_in[5];
    const float* l1_b  = (const float*)d_in[6];
    const float* l2_w  = (const float*)d_in[7];
    const float* l2_b  = (const float*)d_in[8];
    const float* l3_w  = (const float*)d_in[9];
    const float* l3_b  = (const float*)d_in[10];
    float* out = (float*)d_out;

    prep_kernel<<<128, 256>>>(l1_w);
    mega_kernel<<<NT + BATCH, T1>>>(wf, bfeat, stm, ft_w, ft_b,
                                    l1_b, l2_w, l2_b, l3_w, l3_b, out, out_size);
}

// round 7
// speedup vs baseline: 1.4340x; 1.4340x over previous
#include <cuda_runtime.h>
#include <cuda_fp16.h>
#include <math.h>

#define BATCH 4096
#define FEAT  40960
#define HID   1024
#define HID2  2048
#define NL1   64
#define NL2   32

// ---------------- static device scratch (no allocs allowed) ----------------
__device__ __half g_ftT[(size_t)FEAT * HID];    // 83.9 MB: ft_w^T [FEAT][HID] fp16
__device__ __half g_h1[(size_t)BATCH * HID2];   // 16.8 MB: clipped FT output fp16
__device__ __half g_l1w[(size_t)NL1 * HID2];    // 256 KB: l1_w fp16
__device__ int    g_done;                       // transpose-completion counter

// =========================================================================
// Prep: reset counter + convert l1_w to fp16.  grid 128 x 256.
// =========================================================================
__global__ __launch_bounds__(256) void prep_kernel(const float* __restrict__ l1_w)
{
    const int i = blockIdx.x * 256 + threadIdx.x;     // 32768 threads
#pragma unroll
    for (int u = 0; u < 4; u++)
        g_l1w[i + u * 32768] = __float2half(l1_w[i + u * 32768]);
    if (i == 0) g_done = 0;
}

// =========================================================================
// Mega-kernel (round-4 proven version, unchanged):
//   CTAs [0, NT)        : transpose ft_w -> g_ftT (fp16), signal.
//   CTAs [NT, NT+BATCH) : scan -> wait -> gather -> h1 (fp16).
// =========================================================================
#define T1      256
#define NT      512
#define MAXIDX  256
#define NTILE_F (FEAT / 32)                 // 1280
#define NTILES  (NTILE_F * (HID / 64))      // 20480

__global__ __launch_bounds__(T1) void mega_kernel(
    const float* __restrict__ wf,    // [B, FEAT]
    const float* __restrict__ bfeat, // [B, FEAT]
    const float* __restrict__ stm,   // [B, 1]
    const float* __restrict__ ftw,   // [HID, FEAT]
    const float* __restrict__ ft_b)  // [HID]
{
    __shared__ union {
        float tile[64][33];
        struct { int idxW[MAXIDX]; int idxB[MAXIDX]; int cw; int cb; } s;
    } sm;

    const int tid = threadIdx.x;

    if (blockIdx.x < NT) {
        // ---------------- transpose: 40 tiles of 64h x 32f per CTA ----------------
        for (int t = blockIdx.x; t < NTILES; t += NT) {
            const int f0 = (t % NTILE_F) * 32;
            const int h0 = (t / NTILE_F) * 64;
#pragma unroll
            for (int u = 0; u < 8; u++) {
                int idx = tid + u * T1;
                int hl = idx >> 5, fl = idx & 31;
                sm.tile[hl][fl] = __ldcs(ftw + (size_t)(h0 + hl) * FEAT + f0 + fl);
            }
            __syncthreads();
#pragma unroll
            for (int u = 0; u < 4; u++) {
                int idx = tid + u * T1;
                int fl = idx >> 5, hp = idx & 31;
                __half2 v = __floats2half2_rn(sm.tile[2 * hp][fl], sm.tile[2 * hp + 1][fl]);
                *reinterpret_cast<__half2*>(g_ftT + (size_t)(f0 + fl) * HID + h0 + 2 * hp) = v;
            }
            __syncthreads();
        }
        __threadfence();
        __syncthreads();
        if (tid == 0) atomicAdd(&g_done, 1);
        return;
    }

    // ---------------- scan ----------------
    const int b = blockIdx.x - NT;

    if (tid == 0) { sm.s.cw = 0; sm.s.cb = 0; }
    __syncthreads();
    {
        const float4* pw = (const float4*)(wf    + (size_t)b * FEAT);
        const float4* pb = (const float4*)(bfeat + (size_t)b * FEAT);
        for (int base = 0; base < FEAT / 4; base += 4 * T1) {
            float4 v[4], w[4];
#pragma unroll
            for (int u = 0; u < 4; u++) {
                v[u] = __ldcs(pw + base + tid + u * T1);
                w[u] = __ldcs(pb + base + tid + u * T1);
            }
#pragma unroll
            for (int u = 0; u < 4; u++) {
                int i = base + tid + u * T1;
                if (v[u].x != 0.f) { int q = atomicAdd(&sm.s.cw, 1); if (q < MAXIDX) sm.s.idxW[q] = 4*i;   }
                if (v[u].y != 0.f) { int q = atomicAdd(&sm.s.cw, 1); if (q < MAXIDX) sm.s.idxW[q] = 4*i+1; }
                if (v[u].z != 0.f) { int q = atomicAdd(&sm.s.cw, 1); if (q < MAXIDX) sm.s.idxW[q] = 4*i+2; }
                if (v[u].w != 0.f) { int q = atomicAdd(&sm.s.cw, 1); if (q < MAXIDX) sm.s.idxW[q] = 4*i+3; }
                if (w[u].x != 0.f) { int q = atomicAdd(&sm.s.cb, 1); if (q < MAXIDX) sm.s.idxB[q] = 4*i;   }
                if (w[u].y != 0.f) { int q = atomicAdd(&sm.s.cb, 1); if (q < MAXIDX) sm.s.idxB[q] = 4*i+1; }
                if (w[u].z != 0.f) { int q = atomicAdd(&sm.s.cb, 1); if (q < MAXIDX) sm.s.idxB[q] = 4*i+2; }
                if (w[u].w != 0.f) { int q = atomicAdd(&sm.s.cb, 1); if (q < MAXIDX) sm.s.idxB[q] = 4*i+3; }
            }
        }
    }
    __syncthreads();

    // wait for transpose completion
    if (tid == 0) {
        while (atomicAdd(&g_done, 0) < NT) __nanosleep(128);
    }
    __syncthreads();
    __threadfence();

    // ---------------- gather ----------------
    const float4 bias = *reinterpret_cast<const float4*>(ft_b + 4 * tid);
    float4 accW = bias, accB = bias;
    const int nW = min(sm.s.cw, MAXIDX);
#pragma unroll 4
    for (int j = 0; j < nW; j++) {
        const uint2 raw = *reinterpret_cast<const uint2*>(
            g_ftT + (size_t)sm.s.idxW[j] * HID + 4 * tid);
        const float2 lo = __half22float2(*reinterpret_cast<const __half2*>(&raw.x));
        const float2 hi = __half22float2(*reinterpret_cast<const __half2*>(&raw.y));
        accW.x += lo.x; accW.y += lo.y; accW.z += hi.x; accW.w += hi.y;
    }
    const int nB = min(sm.s.cb, MAXIDX);
#pragma unroll 4
    for (int j = 0; j < nB; j++) {
        const uint2 raw = *reinterpret_cast<const uint2*>(
            g_ftT + (size_t)sm.s.idxB[j] * HID + 4 * tid);
        const float2 lo = __half22float2(*reinterpret_cast<const __half2*>(&raw.x));
        const float2 hi = __half22float2(*reinterpret_cast<const __half2*>(&raw.y));
        accB.x += lo.x; accB.y += lo.y; accB.z += hi.x; accB.w += hi.y;
    }

    // stm select + clip + store h1 (fp16)
    const float s = __ldg(stm + b);
    float cw[4] = {fminf(fmaxf(accW.x,0.f),1.f), fminf(fmaxf(accW.y,0.f),1.f),
                   fminf(fmaxf(accW.z,0.f),1.f), fminf(fmaxf(accW.w,0.f),1.f)};
    float cb[4] = {fminf(fmaxf(accB.x,0.f),1.f), fminf(fmaxf(accB.y,0.f),1.f),
                   fminf(fmaxf(accB.z,0.f),1.f), fminf(fmaxf(accB.w,0.f),1.f)};
    __half* o = g_h1 + (size_t)b * HID2;
    uint2 pf, ps;
    *reinterpret_cast<__half2*>(&pf.x) = __floats2half2_rn(
        s*cw[0]+(1.f-s)*cb[0], s*cw[1]+(1.f-s)*cb[1]);
    *reinterpret_cast<__half2*>(&pf.y) = __floats2half2_rn(
        s*cw[2]+(1.f-s)*cb[2], s*cw[3]+(1.f-s)*cb[3]);
    *reinterpret_cast<__half2*>(&ps.x) = __floats2half2_rn(
        s*cb[0]+(1.f-s)*cw[0], s*cb[1]+(1.f-s)*cw[1]);
    *reinterpret_cast<__half2*>(&ps.y) = __floats2half2_rn(
        s*cb[2]+(1.f-s)*cw[2], s*cb[3]+(1.f-s)*cw[3]);
    *reinterpret_cast<uint2*>(o + 4 * tid)       = pf;
    *reinterpret_cast<uint2*>(o + HID + 4 * tid) = ps;
}

// =========================================================================
// Kernel 2: MLP head. TB=16 rows/CTA -> 256 CTAs. 256 threads.
// Thread tile: 2 rows x 2 outs. fp16 weights (L2-resident, single 256 KB copy).
// Register-staged double buffering, one barrier per chunk.
// =========================================================================
#define T2    256
#define TB    16
#define CHUNK 64
#define NCH   (HID2 / CHUNK)   // 32
#define HPAD  20               // hst row stride (floats)
#define WPAD  66               // wst row stride (halves), even

__global__ __launch_bounds__(T2) void mlp_kernel(
    const float* __restrict__ l1_b,
    const float* __restrict__ l2_w, const float* __restrict__ l2_b,
    const float* __restrict__ l3_w, const float* __restrict__ l3_b,
    float* __restrict__ out, int out_size)
{
    __shared__ __align__(16) float  hst[2][CHUNK][HPAD];   // 10.2 KB
    __shared__ __align__(4)  __half wst[2][CHUNK][WPAD];   // 16.9 KB
    __shared__ float l2s[NL2][NL1 + 1];                    // 8.3 KB
    __shared__ float h2s[TB][NL1 + 1];
    __shared__ float h3s[TB][NL2 + 1];

    const int tid  = threadIdx.x;
    const int row0 = blockIdx.x * TB;
    const int tx   = tid & 31;   // out pair {2tx, 2tx+1}
    const int ty   = tid >> 5;   // row pair {2ty, 2ty+1}

    for (int i = tid; i < NL2 * NL1; i += T2) l2s[i >> 6][i & 63] = l2_w[i];

    const __half2* l1w2 = reinterpret_cast<const __half2*>(g_l1w);

    __half2 hreg[2], wreg[8];
    // stage chunk 0
    {
#pragma unroll
        for (int u = 0; u < 2; u++) {
            int idx = tid + u * T2; int r = idx >> 5, kp = idx & 31;
            hreg[u] = *reinterpret_cast<const __half2*>(
                g_h1 + (size_t)(row0 + r) * HID2 + 2 * kp);
        }
#pragma unroll
        for (int u = 0; u < 8; u++) {
            int idx = tid + u * T2; int oo = idx >> 5, kp = idx & 31;
            wreg[u] = __ldg(l1w2 + (size_t)oo * (HID2 / 2) + kp);
        }
#pragma unroll
        for (int u = 0; u < 2; u++) {
            int idx = tid + u * T2; int r = idx >> 5, kp = idx & 31;
            float2 f = __half22float2(hreg[u]);
            hst[0][2 * kp][r]     = f.x;
            hst[0][2 * kp + 1][r] = f.y;
        }
#pragma unroll
        for (int u = 0; u < 8; u++) {
            int idx = tid + u * T2; int oo = idx >> 5, kp = idx & 31;
            wst[0][2 * kp][oo]     = __low2half(wreg[u]);
            wst[0][2 * kp + 1][oo] = __high2half(wreg[u]);
        }
    }
    __syncthreads();

    float acc[2][2];
    acc[0][0] = acc[0][1] = acc[1][0] = acc[1][1] = 0.f;

    for (int c = 0; c < NCH; c++) {
        const int buf = c & 1;
        if (c + 1 < NCH) {
            const int kc = (c + 1) * CHUNK;
#pragma unroll
            for (int u = 0; u < 2; u++) {
                int idx = tid + u * T2; int r = idx >> 5, kp = idx & 31;
                hreg[u] = *reinterpret_cast<const __half2*>(
                    g_h1 + (size_t)(row0 + r) * HID2 + kc + 2 * kp);
            }
#pragma unroll
            for (int u = 0; u < 8; u++) {
                int idx = tid + u * T2; int oo = idx >> 5, kp = idx & 31;
                wreg[u] = __ldg(l1w2 + (size_t)oo * (HID2 / 2) + kc / 2 + kp);
            }
        }
#pragma unroll 16
        for (int k = 0; k < CHUNK; k++) {
            const float2 h = *reinterpret_cast<const float2*>(&hst[buf][k][2 * ty]);
            const float2 w = __half22float2(
                *reinterpret_cast<const __half2*>(&wst[buf][k][2 * tx]));
            acc[0][0] = fmaf(h.x, w.x, acc[0][0]); acc[0][1] = fmaf(h.x, w.y, acc[0][1]);
            acc[1][0] = fmaf(h.y, w.x, acc[1][0]); acc[1][1] = fmaf(h.y, w.y, acc[1][1]);
        }
        if (c + 1 < NCH) {
            const int nb = (c + 1) & 1;
#pragma unroll
            for (int u = 0; u < 2; u++) {
                int idx = tid + u * T2; int r = idx >> 5, kp = idx & 31;
                float2 f = __half22float2(hreg[u]);
                hst[nb][2 * kp][r]     = f.x;
                hst[nb][2 * kp + 1][r] = f.y;
            }
#pragma unroll
            for (int u = 0; u < 8; u++) {
                int idx = tid + u * T2; int oo = idx >> 5, kp = idx & 31;
                wst[nb][2 * kp][oo]     = __low2half(wreg[u]);
                wst[nb][2 * kp + 1][oo] = __high2half(wreg[u]);
            }
        }
        __syncthreads();
    }

    // h2 = clip(l1 + bias)
#pragma unroll
    for (int i = 0; i < 2; i++) {
#pragma unroll
        for (int j = 0; j < 2; j++) {
            float v = acc[i][j] + __ldg(l1_b + 2 * tx + j);
            h2s[2 * ty + i][2 * tx + j] = fminf(fmaxf(v, 0.f), 1.f);
        }
    }
    __syncthreads();

    // l2: 16 rows x 32 outs = 512 -> 2 per thread
    for (int p = tid; p < TB * NL2; p += T2) {
        int r = p >> 5, oo = p & 31;
        float s = __ldg(l2_b + oo);
#pragma unroll
        for (int k = 0; k < NL1; k++) s = fmaf(h2s[r][k], l2s[oo][k], s);
        h3s[r][oo] = fminf(fmaxf(s, 0.f), 1.f);
    }
    __syncthreads();

    // l3 + sigmoid
    if (tid < TB) {
        float s = __ldg(l3_b);
#pragma unroll
        for (int k = 0; k < NL2; k++) s = fmaf(h3s[tid][k], __ldg(l3_w + k), s);
        float sig = 1.f / (1.f + expf(-s));
        int r = row0 + tid;
        if (out_size >= 2 * BATCH) {
            out[r]         = sig;
            out[BATCH + r] = s;
        } else {
            out[r] = sig;
        }
    }
}

// =========================================================================
extern "C" void kernel_launch(void* const* d_in, const int* in_sizes, int n_in,
                              void* d_out, int out_size)
{
    const float* wf    = (const float*)d_in[0];
    const float* bfeat = (const float*)d_in[1];
    const float* stm   = (const float*)d_in[2];
    const float* ft_w  = (const float*)d_in[3];
    const float* ft_b  = (const float*)d_in[4];
    const float* l1_w  = (const float*)d_in[5];
    const float* l1_b  = (const float*)d_in[6];
    const float* l2_w  = (const float*)d_in[7];
    const float* l2_b  = (const float*)d_in[8];
    const float* l3_w  = (const float*)d_in[9];
    const float* l3_b  = (const float*)d_in[10];
    float* out = (float*)d_out;

    prep_kernel<<<128, 256>>>(l1_w);
    mega_kernel<<<NT + BATCH, T1>>>(wf, bfeat, stm, ft_w, ft_b);
    mlp_kernel<<<BATCH / TB, T2>>>(l1_b, l2_w, l2_b, l3_w, l3_b, out, out_size);
}